// round 10
// baseline (speedup 1.0000x reference)
#include <cuda_runtime.h>
#include <cuda_bf16.h>
#include <cstdint>

// Problem shapes
#define B_ 16
#define T_ 24
#define N_ 512
#define D_ 128
#define Z_ 12
#define NEG_SLOPE 0.01f

#define MROWS 32           // rows per CTA -> grid 256
#define NCHUNK 3           // K chunks of 128

// interleaved hi/lo layout: per row 512B: 8 kk-groups x 4 x [h01,l01,h23,l23]
#define RSTRIDE 544        // 512B data + 32B pad (8-bank row shift)
#define OFF_A 0
#define OFF_B (32 * RSTRIDE)                    // 17408
#define SMEM_BYTES (OFF_B + 128 * RSTRIDE)      // 87040
#define YSTRIDE 132        // Ys[32][132] floats = 16896B, fits in A region

// pre-split operands in the exact smem row image (L2-resident)
__device__ __align__(16) uint8_t ASP[NCHUNK][8192][512];   // 12.6 MB
__device__ __align__(16) uint8_t BSP[NCHUNK][128][512];    // 192 KB

// split pair (a,b) -> hi bf16x2 (truncated) + lo bf16x2 (residual, truncated)
__device__ __forceinline__ uint32_t split_pair(float a, float b, uint32_t& lo) {
    uint32_t ia = __float_as_uint(a), ib = __float_as_uint(b);
    uint32_t hi = __byte_perm(ia, ib, 0x7632);
    float ra = a - __uint_as_float(ia & 0xFFFF0000u);
    float rb = b - __uint_as_float(ib & 0xFFFF0000u);
    lo = __byte_perm(__float_as_uint(ra), __float_as_uint(rb), 0x7632);
    return hi;
}
__device__ __forceinline__ void mma16816(float* c, const uint32_t* a, uint32_t b0, uint32_t b1) {
    asm volatile(
        "mma.sync.aligned.m16n8k16.row.col.f32.bf16.bf16.f32 "
        "{%0,%1,%2,%3},{%4,%5,%6,%7},{%8,%9},{%0,%1,%2,%3};"
        : "+f"(c[0]), "+f"(c[1]), "+f"(c[2]), "+f"(c[3])
        : "r"(a[0]), "r"(a[1]), "r"(a[2]), "r"(a[3]), "r"(b0), "r"(b1));
}
__device__ __forceinline__ uint32_t smem_u32(const void* p) {
    uint32_t a;
    asm("{ .reg .u64 t; cvta.to.shared.u64 t, %1; cvt.u32.u64 %0, t; }" : "=r"(a) : "l"(p));
    return a;
}
__device__ __forceinline__ void cp_async16(uint32_t dst, const void* src) {
    asm volatile("cp.async.cg.shared.global [%0], [%1], 16;" :: "r"(dst), "l"(src) : "memory");
}
#define CP_COMMIT() asm volatile("cp.async.commit_group;" ::: "memory")
#define CP_WAIT0()  asm volatile("cp.async.wait_group 0;" ::: "memory")

// ---- prep: split A (live input rows) and W1 into smem-image layout ----
__global__ void __launch_bounds__(256)
prep_kernel(const float* __restrict__ Ht, const float* __restrict__ Hs,
            const float* __restrict__ Hm, const float* __restrict__ W1)
{
    int bid = blockIdx.x;
    if (bid < 3072) {            // A: 3 chunks x 8192 rows x 32 float4
        int idx = bid * 256 + threadIdx.x;          // 0..786431
        int c = idx / 262144;
        int rem = idx - c * 262144;
        int r = rem >> 5, f4 = rem & 31;
        const float* src = (c == 0) ? Ht : ((c == 1) ? Hs : Hm);
        int b = r >> 9, n = r & 511;
        float4 v = *reinterpret_cast<const float4*>(
            src + (((size_t)b * T_ + (T_ - 1)) * N_ + n) * D_ + f4 * 4);
        uint32_t l01, l23;
        uint32_t h01 = split_pair(v.x, v.y, l01);
        uint32_t h23 = split_pair(v.z, v.w, l23);
        *reinterpret_cast<uint4*>(&ASP[c][r][(f4 >> 2) * 64 + (f4 & 3) * 16])
            = make_uint4(h01, l01, h23, l23);
    } else {                     // B: 3 chunks x 128 rows x 32 float4
        int idx = (bid - 3072) * 256 + threadIdx.x; // 0..12287
        int c = idx / 4096;
        int rem = idx & 4095;
        int n = rem >> 5, f4 = rem & 31;
        float4 v = *reinterpret_cast<const float4*>(W1 + (size_t)n * 384 + c * 128 + f4 * 4);
        uint32_t l01, l23;
        uint32_t h01 = split_pair(v.x, v.y, l01);
        uint32_t h23 = split_pair(v.z, v.w, l23);
        *reinterpret_cast<uint4*>(&BSP[c][n][(f4 >> 2) * 64 + (f4 & 3) * 16])
            = make_uint4(h01, l01, h23, l23);
    }
}

__global__ void __launch_bounds__(256, 2)
fusion_mma_kernel(const float* __restrict__ b1,   // [128]
                  const float* __restrict__ W2,   // [12][128]
                  const float* __restrict__ b2,   // [12]
                  float* __restrict__ out)        // [16][12][512]
{
    extern __shared__ char smem[];
    const uint32_t sb = smem_u32(smem);
    const int tid  = threadIdx.x;
    const int wid  = tid >> 5;
    const int lane = tid & 31;
    const int g    = lane >> 2;      // 0..7
    const int t    = lane & 3;       // 0..3
    const int wm   = wid >> 2;       // 0..1 -> rows wm*16
    const int wn   = wid & 3;        // 0..3 -> cols wn*32
    const int rowBase = blockIdx.x * MROWS;

    float acc[4][4];
    #pragma unroll
    for (int j = 0; j < 4; ++j)
        #pragma unroll
        for (int i = 0; i < 4; ++i) acc[j][i] = 0.f;

    // fragment base addresses (R7 layout, unchanged)
    const char* Ab = smem + OFF_A + (wm * 16 + g) * RSTRIDE + t * 8;
    const char* Bb = smem + OFF_B + (wn * 32 + g) * RSTRIDE + t * 8;

    #pragma unroll
    for (int c = 0; c < NCHUNK; ++c) {
        // ---- cp.async A: 32 rows x 512B ----
        #pragma unroll
        for (int i = 0; i < 4; ++i) {
            int idx = i * 256 + tid;
            int row = idx >> 5, c16 = idx & 31;
            cp_async16(sb + OFF_A + row * RSTRIDE + c16 * 16,
                       &ASP[c][rowBase + row][c16 * 16]);
        }
        // ---- cp.async B: 128 rows x 512B ----
        #pragma unroll
        for (int i = 0; i < 16; ++i) {
            int idx = i * 256 + tid;
            int row = idx >> 5, c16 = idx & 31;
            cp_async16(sb + OFF_B + row * RSTRIDE + c16 * 16,
                       &BSP[c][row][c16 * 16]);
        }
        CP_COMMIT();
        CP_WAIT0();
        __syncthreads();

        // ---- MMA: 8 k16-steps x 4 n-tiles x 3 terms ----
        #pragma unroll
        for (int kk = 0; kk < 8; ++kk) {
            uint2 qa0 = *reinterpret_cast<const uint2*>(Ab + kk * 64);
            uint2 qa1 = *reinterpret_cast<const uint2*>(Ab + kk * 64 + 8 * RSTRIDE);
            uint2 qa2 = *reinterpret_cast<const uint2*>(Ab + kk * 64 + 32);
            uint2 qa3 = *reinterpret_cast<const uint2*>(Ab + kk * 64 + 8 * RSTRIDE + 32);
            uint32_t ah[4] = {qa0.x, qa1.x, qa2.x, qa3.x};
            uint32_t al[4] = {qa0.y, qa1.y, qa2.y, qa3.y};
            #pragma unroll
            for (int j = 0; j < 4; ++j) {
                uint2 qb0 = *reinterpret_cast<const uint2*>(Bb + j * 8 * RSTRIDE + kk * 64);
                uint2 qb1 = *reinterpret_cast<const uint2*>(Bb + j * 8 * RSTRIDE + kk * 64 + 32);
                mma16816(acc[j], ah, qb0.x, qb1.x);   // hi*hi
                mma16816(acc[j], ah, qb0.y, qb1.y);   // hi*lo
                mma16816(acc[j], al, qb0.x, qb1.x);   // lo*hi
            }
        }
        __syncthreads();
    }

    // ---- epilogue: bias + LeakyReLU -> Ys smem (reuses A region) ----
    float* Ys = reinterpret_cast<float*>(smem);
    #pragma unroll
    for (int j = 0; j < 4; ++j) {
        int col = wn * 32 + j * 8 + 2 * t;
        float bv0 = __ldg(b1 + col), bv1 = __ldg(b1 + col + 1);
        int row0 = wm * 16 + g;
        float y0 = acc[j][0] + bv0; y0 = (y0 > 0.f) ? y0 : NEG_SLOPE * y0;
        float y1 = acc[j][1] + bv1; y1 = (y1 > 0.f) ? y1 : NEG_SLOPE * y1;
        float y2 = acc[j][2] + bv0; y2 = (y2 > 0.f) ? y2 : NEG_SLOPE * y2;
        float y3 = acc[j][3] + bv1; y3 = (y3 > 0.f) ? y3 : NEG_SLOPE * y3;
        *reinterpret_cast<float2*>(Ys + row0 * YSTRIDE + col)       = make_float2(y0, y1);
        *reinterpret_cast<float2*>(Ys + (row0 + 8) * YSTRIDE + col) = make_float2(y2, y3);
    }
    __syncthreads();

    // ---- GEMM2: 32 rows x 12 z = 384 outputs ----
    #pragma unroll
    for (int it = 0; it < 2; ++it) {
        int o = it * 256 + tid;
        if (o < MROWS * Z_) {
            int r = o / Z_, z = o - r * Z_;
            float s = __ldg(b2 + z);
            const float4* w = reinterpret_cast<const float4*>(W2 + (size_t)z * D_);
            const float4* y = reinterpret_cast<const float4*>(Ys + r * YSTRIDE);
            #pragma unroll 8
            for (int d4 = 0; d4 < 32; ++d4) {
                float4 wv = __ldg(w + d4);
                float4 yv = y[d4];
                s += yv.x * wv.x + yv.y * wv.y + yv.z * wv.z + yv.w * wv.w;
            }
            int grp = rowBase + r;
            int b = grp >> 9, n = grp & 511;
            out[((size_t)b * Z_ + z) * N_ + n] = s;
        }
    }
}

extern "C" void kernel_launch(void* const* d_in, const int* in_sizes, int n_in,
                              void* d_out, int out_size)
{
    const float* Ht = (const float*)d_in[0];
    const float* Hs = (const float*)d_in[1];
    const float* Hm = (const float*)d_in[2];
    const float* W1 = (const float*)d_in[3];
    const float* b1 = (const float*)d_in[4];
    const float* W2 = (const float*)d_in[5];
    const float* b2 = (const float*)d_in[6];
    float* out = (float*)d_out;

    prep_kernel<<<3072 + 48, 256>>>(Ht, Hs, Hm, W1);

    cudaFuncSetAttribute(fusion_mma_kernel,
                         cudaFuncAttributeMaxDynamicSharedMemorySize, SMEM_BYTES);
    int grid = (B_ * N_) / MROWS;   // 256 CTAs
    fusion_mma_kernel<<<grid, 256, SMEM_BYTES>>>(b1, W2, b2, out);
}